// round 15
// baseline (speedup 1.0000x reference)
#include <cuda_runtime.h>
#include <cuda_bf16.h>
#include <math.h>
#include <stdint.h>

#define N 6144
#define F 128
#define H 128
#define E_EDGES 16384
#define TOPK 32
#define MAXNNZ 96

// ------------------- device scratch -------------------
__device__ float g_nbr_val[N * MAXNNZ];
__device__ int   g_nbr_idx[N * MAXNNZ];
__device__ int   g_nnz[N];
__device__ float g_isr[N];
__device__ float g_isc[N];
__device__ int   g_colcnt[N];
__device__ float g_sim[(size_t)N * N];
__device__ __nv_bfloat16 g_xhib[N * F];
__device__ __nv_bfloat16 g_xlob[N * F];
__device__ float g_tkw[N * TOPK];
__device__ int   g_tki[N * TOPK];
__device__ float g_bufA[N * H];
__device__ float g_bufB[N * H];
__device__ float g_bufD[N * H];
__device__ float g_bufE[N * H];
__device__ float g_bufF[N * H];
__device__ float g_g[N * 2 * H];

__device__ __forceinline__ uint32_t smem_u32(const void* p) {
    uint32_t a;
    asm("{ .reg .u64 t; cvta.to.shared.u64 t, %1; cvt.u32.u64 %0, t; }" : "=r"(a) : "l"(p));
    return a;
}
__device__ __forceinline__ void cp16(uint32_t s, const float* g) {
    asm volatile("cp.async.cg.shared.global [%0], [%1], 16;" :: "r"(s), "l"(g));
}
#define CP_COMMIT() asm volatile("cp.async.commit_group;")
#define CP_WAIT2()  asm volatile("cp.async.wait_group 2;")

#define LDMX4(r, addr) \
    asm volatile("ldmatrix.sync.aligned.m8n8.x4.shared.b16 {%0,%1,%2,%3}, [%4];" \
        : "=r"((r)[0]), "=r"((r)[1]), "=r"((r)[2]), "=r"((r)[3]) : "r"(addr))

#define MMA_BF16(c, a, b0, b1) \
    asm volatile("mma.sync.aligned.m16n8k16.row.col.f32.bf16.bf16.f32 " \
        "{%0,%1,%2,%3}, {%4,%5,%6,%7}, {%8,%9}, {%0,%1,%2,%3};" \
        : "+f"((c)[0]), "+f"((c)[1]), "+f"((c)[2]), "+f"((c)[3]) \
        : "r"((a)[0]), "r"((a)[1]), "r"((a)[2]), "r"((a)[3]), "r"(b0), "r"(b1))

// ------------------- adj: CSR + row sums + col counts -------------------
__global__ void zero_colcnt() {
    int j = blockIdx.x * blockDim.x + threadIdx.x;
    if (j < N) g_colcnt[j] = 0;
}

__global__ void build_csr(const float* __restrict__ adj) {
    int row  = blockIdx.x * (blockDim.x >> 5) + (threadIdx.x >> 5);
    int lane = threadIdx.x & 31;
    if (row >= N) return;
    const float* arow = adj + (size_t)row * N;
    float s = 0.f;
    int base = 0;
    for (int c = 0; c < N; c += 32) {
        float v = arow[c + lane];
        s += v;
        unsigned b = __ballot_sync(0xffffffffu, v != 0.f);
        if (v != 0.f) {
            int pos = base + __popc(b & ((1u << lane) - 1u));
            if (pos < MAXNNZ) {
                g_nbr_idx[row * MAXNNZ + pos] = c + lane;
                g_nbr_val[row * MAXNNZ + pos] = v;
            }
            atomicAdd(&g_colcnt[c + lane], 1);
        }
        base += __popc(b);
    }
    for (int o = 16; o; o >>= 1) s += __shfl_xor_sync(0xffffffffu, s, o);
    if (lane == 0) {
        g_nnz[row] = base < MAXNNZ ? base : MAXNNZ;
        g_isr[row] = 1.f / sqrtf(s + 1.f);
    }
}

__global__ void colcnt_to_isc() {
    int j = blockIdx.x * blockDim.x + threadIdx.x;
    if (j < N) g_isc[j] = 1.f / sqrtf((float)g_colcnt[j] + 1.f);
}

// ------------------- fused row norms + NORMALIZE + bf16 hi/lo split -------------------
__global__ void norm_split(const float* __restrict__ x) {
    int row  = blockIdx.x * (blockDim.x >> 5) + (threadIdx.x >> 5);
    int lane = threadIdx.x & 31;
    if (row >= N) return;
    float v[4];
    float s = 0.f;
#pragma unroll
    for (int u = 0; u < 4; u++) {
        v[u] = x[(size_t)row * F + lane + 32 * u];
        s += v[u] * v[u];
    }
    for (int o = 16; o; o >>= 1) s += __shfl_xor_sync(0xffffffffu, s, o);
    float inv = 1.f / sqrtf(s);
#pragma unroll
    for (int u = 0; u < 4; u++) {
        size_t i = (size_t)row * F + lane + 32 * u;
        float xn = v[u] * inv;
        __nv_bfloat16 hi = __float2bfloat16(xn);
        g_xhib[i] = hi;
        g_xlob[i] = __float2bfloat16(xn - __bfloat162float(hi));
    }
}

// ------------------- sim GEMM (128x64 tiles, fused 3-term k-loop) -------------------
#define RS 136
#define OFF_AHI 0
#define OFF_ALO (OFF_AHI + 128 * RS * 2)
#define OFF_BHI (OFF_ALO + 128 * RS * 2)
#define OFF_BLO (OFF_BHI + 64 * RS * 2)
#define SIM_SMEM (OFF_BLO + 64 * RS * 2)

__global__ void __launch_bounds__(256, 2) simgemm_mma() {
    extern __shared__ char sm[];
    uint32_t sb = smem_u32(sm);
    int tid = threadIdx.x;
    int wid = tid >> 5, lane = tid & 31;

    int blk = blockIdx.x, bi = 0;
    while (blk >= 96 - 2 * bi) { blk -= 96 - 2 * bi; bi++; }
    int bj = 2 * bi + blk;
    int i0 = bi * 128, j0 = bj * 64;
    bool do_mirror = (bj >= 2 * bi + 2);

    {
        const uint4* shi = (const uint4*)g_xhib;
        const uint4* slo = (const uint4*)g_xlob;
        for (int idx = tid; idx < 128 * 16; idx += 256) {
            int r = idx >> 4, c = idx & 15;
            size_t gi = (size_t)(i0 + r) * 16 + c;
            uint32_t o = (uint32_t)(r * (RS * 2) + c * 16);
            *(uint4*)(sm + OFF_AHI + o) = shi[gi];
            *(uint4*)(sm + OFF_ALO + o) = slo[gi];
        }
        for (int idx = tid; idx < 64 * 16; idx += 256) {
            int r = idx >> 4, c = idx & 15;
            size_t gi = (size_t)(j0 + r) * 16 + c;
            uint32_t o = (uint32_t)(r * (RS * 2) + c * 16);
            *(uint4*)(sm + OFF_BHI + o) = shi[gi];
            *(uint4*)(sm + OFF_BLO + o) = slo[gi];
        }
    }
    __syncthreads();

    int wr = wid >> 1, wc = wid & 1;
    float acc[2][4][4];
#pragma unroll
    for (int mi = 0; mi < 2; mi++)
#pragma unroll
        for (int nj = 0; nj < 4; nj++)
#pragma unroll
            for (int q = 0; q < 4; q++) acc[mi][nj][q] = 0.f;

    uint32_t aoff = (uint32_t)((wr * 32 + (lane & 15)) * (RS * 2) + ((lane >> 4) << 4));
    uint32_t boff = (uint32_t)((wc * 32 + ((lane >> 4) << 3) + (lane & 7)) * (RS * 2)
                               + (((lane >> 3) & 1) << 4));
    uint32_t aHi = sb + OFF_AHI + aoff, aLo = sb + OFF_ALO + aoff;
    uint32_t bHi = sb + OFF_BHI + boff, bLo = sb + OFF_BLO + boff;

#pragma unroll
    for (int kk = 0; kk < 8; kk++) {
        uint32_t arh[2][4], arl[2][4], brh[2][4], brl[2][4];
        LDMX4(arh[0], aHi + kk * 32);
        LDMX4(arh[1], aHi + 16 * (RS * 2) + kk * 32);
        LDMX4(brh[0], bHi + kk * 32);
        LDMX4(brh[1], bHi + 16 * (RS * 2) + kk * 32);
        LDMX4(arl[0], aLo + kk * 32);
        LDMX4(arl[1], aLo + 16 * (RS * 2) + kk * 32);
        LDMX4(brl[0], bLo + kk * 32);
        LDMX4(brl[1], bLo + 16 * (RS * 2) + kk * 32);
#pragma unroll
        for (int mi = 0; mi < 2; mi++) {
            MMA_BF16(acc[mi][0], arh[mi], brh[0][0], brh[0][1]);
            MMA_BF16(acc[mi][1], arh[mi], brh[0][2], brh[0][3]);
            MMA_BF16(acc[mi][2], arh[mi], brh[1][0], brh[1][1]);
            MMA_BF16(acc[mi][3], arh[mi], brh[1][2], brh[1][3]);
            MMA_BF16(acc[mi][0], arh[mi], brl[0][0], brl[0][1]);
            MMA_BF16(acc[mi][1], arh[mi], brl[0][2], brl[0][3]);
            MMA_BF16(acc[mi][2], arh[mi], brl[1][0], brl[1][1]);
            MMA_BF16(acc[mi][3], arh[mi], brl[1][2], brl[1][3]);
            MMA_BF16(acc[mi][0], arl[mi], brh[0][0], brh[0][1]);
            MMA_BF16(acc[mi][1], arl[mi], brh[0][2], brh[0][3]);
            MMA_BF16(acc[mi][2], arl[mi], brh[1][0], brh[1][1]);
            MMA_BF16(acc[mi][3], arl[mi], brh[1][2], brh[1][3]);
        }
    }
    __syncthreads();

    float* Cs = (float*)(sm + OFF_AHI);  // 128 x 65
    {
        int rbase = wr * 32 + (lane >> 2);
        int cbase = wc * 32 + ((lane & 3) << 1);
#pragma unroll
        for (int mi = 0; mi < 2; mi++) {
            int r = rbase + mi * 16;
#pragma unroll
            for (int nj = 0; nj < 4; nj++) {
                int c = cbase + nj * 8;
                Cs[r * 65 + c]           = acc[mi][nj][0];
                Cs[r * 65 + c + 1]       = acc[mi][nj][1];
                Cs[(r + 8) * 65 + c]     = acc[mi][nj][2];
                Cs[(r + 8) * 65 + c + 1] = acc[mi][nj][3];
            }
        }
    }
    __syncthreads();

#pragma unroll
    for (int k = 0; k < 32; k++) {
        int idx = tid + k * 256;
        int r = idx >> 6, c = idx & 63;
        g_sim[(size_t)(i0 + r) * N + (j0 + c)] = Cs[r * 65 + c];
    }
    if (do_mirror) {
#pragma unroll
        for (int k = 0; k < 32; k++) {
            int idx = tid + k * 256;
            int rr = idx >> 7, cc = idx & 127;
            g_sim[(size_t)(j0 + rr) * N + (i0 + cc)] = Cs[cc * 65 + rr];
        }
    }
}

// ------------------- top-k v3: 3-level 2048-bin radix select (float4 load) -------------------
__device__ __forceinline__ unsigned f2key(float v) {
    unsigned u = __float_as_uint(v);
    return (u & 0x80000000u) ? ~u : (u | 0x80000000u);
}
__device__ __forceinline__ float key2f(unsigned k) {
    unsigned u = (k & 0x80000000u) ? (k & 0x7FFFFFFFu) : ~k;
    return __uint_as_float(u);
}

template<int NB>
__device__ __forceinline__ void find_cross(const int* hist, int* wsum, int nd,
                                           int tid, int lane, int wid,
                                           int* s_bin, int* s_need) {
    const int PER = NB / 256;
    int base = tid * PER;
    int h[PER];
    int lsum = 0;
#pragma unroll
    for (int j = 0; j < PER; j++) { h[j] = hist[base + j]; lsum += h[j]; }
    int v = lsum;
#pragma unroll
    for (int d = 1; d < 32; d <<= 1) {
        int n = __shfl_up_sync(0xffffffffu, v, d);
        if (lane >= d) v += n;
    }
    if (lane == 31) wsum[wid] = v;
    __syncthreads();
    if (tid < 8) {
        int w = wsum[tid];
#pragma unroll
        for (int d = 1; d < 8; d <<= 1) {
            int n = __shfl_up_sync(0xffu, w, d);
            if (tid >= d) w += n;
        }
        wsum[tid] = w;
    }
    __syncthreads();
    int incl = v + (wid ? wsum[wid - 1] : 0);
    int total = wsum[7];
    int S = total - incl;
#pragma unroll
    for (int j = PER - 1; j >= 0; j--) {
        S += h[j];
        if (S >= nd && S - h[j] < nd) {
            *s_bin = base + j;
            *s_need = nd - (S - h[j]);
        }
    }
}

__global__ void __launch_bounds__(256) topk_kernel() {
    __shared__ unsigned keys[N];
    __shared__ int hist[2048];
    __shared__ int wsum[8];
    __shared__ float outv[TOPK];
    __shared__ int   outi[TOPK];
    __shared__ int s_bin, s_need;
    __shared__ float s_invd;

    int row = blockIdx.x, tid = threadIdx.x;
    int lane = tid & 31, wid = tid >> 5;
    const float4* sr4 = (const float4*)(g_sim + (size_t)row * N);
    const int CH = N / 256;

    for (int i = tid; i < 2048; i += 256) hist[i] = 0;
    __syncthreads();
    // vectorized load + key conversion + level-1 histogram
#pragma unroll
    for (int q = 0; q < 6; q++) {
        int v4 = q * 256 + tid;          // float4 index, 1536 total
        float4 val = sr4[v4];
        int base = v4 * 4;
        float vv[4] = {val.x, val.y, val.z, val.w};
#pragma unroll
        for (int c = 0; c < 4; c++) {
            unsigned k = f2key(vv[c]);
            if (base + c == row) k = 0u;
            keys[base + c] = k;
            atomicAdd(&hist[k >> 21], 1);
        }
    }
    __syncthreads();
    find_cross<2048>(hist, wsum, TOPK, tid, lane, wid, &s_bin, &s_need);
    __syncthreads();
    unsigned b1 = (unsigned)s_bin;
    int nd2 = s_need;
    __syncthreads();

    for (int i = tid; i < 2048; i += 256) hist[i] = 0;
    __syncthreads();
#pragma unroll
    for (int e = 0; e < CH; e++) {
        unsigned k = keys[e * 256 + tid];
        if ((k >> 21) == b1) atomicAdd(&hist[(k >> 10) & 0x7FFu], 1);
    }
    __syncthreads();
    find_cross<2048>(hist, wsum, nd2, tid, lane, wid, &s_bin, &s_need);
    __syncthreads();
    unsigned pre21 = (b1 << 11) | (unsigned)s_bin;
    int nd3 = s_need;
    __syncthreads();

    for (int i = tid; i < 1024; i += 256) hist[i] = 0;
    __syncthreads();
#pragma unroll
    for (int e = 0; e < CH; e++) {
        unsigned k = keys[e * 256 + tid];
        if ((k >> 10) == pre21) atomicAdd(&hist[k & 0x3FFu], 1);
    }
    __syncthreads();
    find_cross<1024>(hist, wsum, nd3, tid, lane, wid, &s_bin, &s_need);
    __syncthreads();
    unsigned T = (pre21 << 10) | (unsigned)s_bin;
    int need_eq = s_need;
    __syncthreads();

    int cg = 0, ce = 0;
#pragma unroll
    for (int e = 0; e < CH; e++) {
        unsigned k = keys[e * 256 + tid];
        cg += (k > T);
        ce += (k == T);
    }
    {
        int v = (cg << 16) | ce;
#pragma unroll
        for (int d = 1; d < 32; d <<= 1) {
            int n = __shfl_up_sync(0xffffffffu, v, d);
            if (lane >= d) v += n;
        }
        if (lane == 31) wsum[wid] = v;
        __syncthreads();
        if (tid < 8) {
            int w = wsum[tid];
#pragma unroll
            for (int d = 1; d < 8; d <<= 1) {
                int n = __shfl_up_sync(0xffu, w, d);
                if (tid >= d) w += n;
            }
            wsum[tid] = w;
        }
        __syncthreads();
        int incl = v + (wid ? wsum[wid - 1] : 0);
        int total = wsum[7];
        int total_g = total >> 16;
        int pg = (incl >> 16) - cg;
        int pe = total_g + ((incl & 0xFFFF) - ce);
#pragma unroll
        for (int e = 0; e < CH; e++) {
            int gi = e * 256 + tid;
            unsigned k = keys[gi];
            if (k > T) {
                outv[pg] = key2f(k); outi[pg] = gi; pg++;
            } else if (k == T) {
                if (pe < total_g + need_eq) { outv[pe] = key2f(k); outi[pe] = gi; }
                pe++;
            }
        }
    }
    __syncthreads();
    if (tid < 32) {
        float s = outv[tid];
        for (int o = 16; o; o >>= 1) s += __shfl_xor_sync(0xffffffffu, s, o);
        if (tid == 0) s_invd = 1.f / fmaxf(s, 1e-5f);
    }
    __syncthreads();
    if (tid < TOPK) {
        g_tkw[row * TOPK + tid] = outv[tid] * s_invd;
        g_tki[row * TOPK + tid] = outi[tid];
    }
}

// ------------------- gemm v4: 2*HOUT threads, RPB=16, 4-buffer cp.async ring -------------------
template<int K, int HOUT>
__global__ void __launch_bounds__(2 * HOUT) gemm_t4(const float* __restrict__ A1,
                                                    const float* __restrict__ A2,
                                                    const float* __restrict__ W,
                                                    const float* __restrict__ bias, int act,
                                                    int accum,
                                                    float* __restrict__ C) {
    const int RPB = 16;
    const int BLK = 2 * HOUT;
    const int CHK = 2048 / HOUT;
    const int NCH = K / CHK;
    const int CBYTES = CHK * HOUT * 4;
    extern __shared__ float dyn[];
    float* wring = dyn;
    float* a_sh  = dyn + 4 * CHK * HOUT;
    uint32_t wsm = smem_u32(wring);

    int tid = threadIdx.x;
    int f  = tid & (HOUT - 1);
    int rh = tid / HOUT;
    int r0 = blockIdx.x * RPB;
    int rbase = rh * 8;

#pragma unroll
    for (int c = 0; c < 2; c++) {
        const float* gW = W + (size_t)c * CHK * HOUT;
        uint32_t dst = wsm + c * CBYTES;
        for (int i = tid; i < CHK * HOUT / 4; i += BLK)
            cp16(dst + (uint32_t)i * 16, gW + (size_t)i * 4);
        CP_COMMIT();
    }

    if (K == 256) {
        for (int idx = tid; idx < RPB * 128; idx += BLK) {
            int r = idx >> 7, k = idx & 127;
            a_sh[r * K + k]       = A1[(size_t)(r0 + r) * 128 + k];
            a_sh[r * K + 128 + k] = A2[(size_t)(r0 + r) * 128 + k];
        }
    } else {
        for (int idx = tid; idx < RPB * K; idx += BLK) {
            int r = idx / K, k = idx & (K - 1);
            a_sh[r * K + k] = A1[(size_t)(r0 + r) * K + k];
        }
    }

    float acc[8];
    if (accum) {
#pragma unroll
        for (int r = 0; r < 8; r++) acc[r] = C[(size_t)(r0 + rbase + r) * HOUT + f];
    } else {
        float b = bias ? bias[f] : 0.f;
#pragma unroll
        for (int r = 0; r < 8; r++) acc[r] = b;
    }

#pragma unroll
    for (int ch = 0; ch < NCH; ch++) {
        if (ch + 2 < NCH) {
            const float* gW = W + (size_t)(ch + 2) * CHK * HOUT;
            uint32_t dst = wsm + ((ch + 2) & 3) * CBYTES;
            for (int i = tid; i < CHK * HOUT / 4; i += BLK)
                cp16(dst + (uint32_t)i * 16, gW + (size_t)i * 4);
        }
        CP_COMMIT();
        CP_WAIT2();
        __syncthreads();

        const float* wp = wring + (ch & 3) * CHK * HOUT;
        int kc = ch * CHK;
#pragma unroll
        for (int kk = 0; kk < CHK; kk += 4) {
            float w0 = wp[kk * HOUT + f];
            float w1 = wp[(kk + 1) * HOUT + f];
            float w2 = wp[(kk + 2) * HOUT + f];
            float w3 = wp[(kk + 3) * HOUT + f];
#pragma unroll
            for (int r = 0; r < 8; r++) {
                float4 av = *(const float4*)&a_sh[(rbase + r) * K + kc + kk];
                acc[r] += av.x * w0 + av.y * w1 + av.z * w2 + av.w * w3;
            }
        }
    }

#pragma unroll
    for (int r = 0; r < 8; r++) {
        float v = acc[r];
        if (act) v = v > 0.f ? v : expm1f(v);
        C[(size_t)(r0 + rbase + r) * HOUT + f] = v;
    }
}

#define G4_128_128 ((4 * 16 * 128 + 16 * 128) * 4)
#define G4_128_256 ((4 * 8 * 256 + 16 * 128) * 4)

// ------------------- fused SAGE: 256 threads, RPB=16 -------------------
__global__ void __launch_bounds__(256) sage_fused(const float* __restrict__ z,
                                                  const float* __restrict__ h,
                                                  const float* __restrict__ W,
                                                  float* __restrict__ C) {
    const int RPB = 16, K = 256, HOUT = 128, BLK = 256;
    const int CHK = 16, NCH = 16;
    const int CBYTES = CHK * HOUT * 4;
    extern __shared__ float dyn[];
    float* wring = dyn;
    float* a_sh  = dyn + 4 * CHK * HOUT;
    float* twv   = a_sh + RPB * K;
    int*   twi   = (int*)(twv + RPB * TOPK);
    uint32_t wsm = smem_u32(wring);

    int tid = threadIdx.x;
    int f  = tid & 127;
    int rh = tid >> 7;
    int r0 = blockIdx.x * RPB;
    int rbase = rh * 8;

#pragma unroll
    for (int c = 0; c < 2; c++) {
        const float* gW = W + (size_t)c * CHK * HOUT;
        uint32_t dst = wsm + c * CBYTES;
        for (int i = tid; i < CHK * HOUT / 4; i += BLK)
            cp16(dst + (uint32_t)i * 16, gW + (size_t)i * 4);
        CP_COMMIT();
    }

    for (int i = tid; i < RPB * TOPK; i += BLK) {
        twv[i] = g_tkw[r0 * TOPK + i];
        twi[i] = g_tki[r0 * TOPK + i];
    }
#pragma unroll
    for (int r = 0; r < 8; r++)
        a_sh[(rbase + r) * K + f] = z[(size_t)(r0 + rbase + r) * 128 + f];
    __syncthreads();

#pragma unroll
    for (int r = 0; r < 8; r++) {
        int rr = rbase + r;
        float acc = 0.f;
#pragma unroll 8
        for (int q = 0; q < TOPK; q++)
            acc += twv[rr * TOPK + q] * h[(size_t)twi[rr * TOPK + q] * 128 + f];
        a_sh[rr * K + 128 + f] = acc;
    }

    float acc[8];
#pragma unroll
    for (int r = 0; r < 8; r++) acc[r] = 0.f;

#pragma unroll
    for (int ch = 0; ch < NCH; ch++) {
        if (ch + 2 < NCH) {
            const float* gW = W + (size_t)(ch + 2) * CHK * HOUT;
            uint32_t dst = wsm + ((ch + 2) & 3) * CBYTES;
            for (int i = tid; i < CHK * HOUT / 4; i += BLK)
                cp16(dst + (uint32_t)i * 16, gW + (size_t)i * 4);
        }
        CP_COMMIT();
        CP_WAIT2();
        __syncthreads();

        const float* wp = wring + (ch & 3) * CHK * HOUT;
        int kc = ch * CHK;
#pragma unroll
        for (int kk = 0; kk < CHK; kk += 4) {
            float w0 = wp[kk * HOUT + f];
            float w1 = wp[(kk + 1) * HOUT + f];
            float w2 = wp[(kk + 2) * HOUT + f];
            float w3 = wp[(kk + 3) * HOUT + f];
#pragma unroll
            for (int r = 0; r < 8; r++) {
                float4 av = *(const float4*)&a_sh[(rbase + r) * K + kc + kk];
                acc[r] += av.x * w0 + av.y * w1 + av.z * w2 + av.w * w3;
            }
        }
    }

#pragma unroll
    for (int r = 0; r < 8; r++) {
        float v = acc[r];
        v = v > 0.f ? v : expm1f(v);
        C[(size_t)(r0 + rbase + r) * HOUT + f] = v;
    }
}
#define SAGE_SMEM ((4 * 16 * 128 + 16 * 256 + 2 * 16 * 32) * 4)

// ------------------- GCN SpMM -------------------
__global__ void gcn_spmm(const float* __restrict__ zw, float* __restrict__ out) {
    int row = blockIdx.x, f = threadIdx.x;
    __shared__ float vv[MAXNNZ];
    __shared__ int   vi[MAXNNZ];
    int nnz = g_nnz[row];
    for (int i = f; i < nnz; i += H) {
        int j = g_nbr_idx[row * MAXNNZ + i];
        vi[i] = j;
        vv[i] = g_nbr_val[row * MAXNNZ + i] * g_isc[j];
    }
    __syncthreads();
    float acc = g_isc[row] * zw[(size_t)row * H + f];
    for (int i = 0; i < nnz; i++) acc += vv[i] * zw[(size_t)vi[i] * H + f];
    float v = acc * g_isr[row];
    out[(size_t)row * H + f] = v > 0.f ? v : expm1f(v);
}

// ------------------- edge logits -------------------
__global__ void edge_kernel(const int* __restrict__ src, const int* __restrict__ dst,
                            const float* __restrict__ g, const float* __restrict__ h1,
                            const float* __restrict__ h2, const float* __restrict__ predB,
                            float* __restrict__ logits) {
    int e = (blockIdx.x * blockDim.x + threadIdx.x) >> 5;
    int lane = threadIdx.x & 31;
    if (e >= E_EDGES) return;
    int s = src[e], d = dst[e];
    const float* gr = g + (size_t)s * (2 * H);
    float acc = 0.f;
#pragma unroll
    for (int u = 0; u < 8; u++) {
        int c = lane + 32 * u;
        float hv = (c < H) ? h1[(size_t)d * H + c] : h2[(size_t)d * H + (c - H)];
        acc += gr[c] * hv;
    }
    for (int o = 16; o; o >>= 1) acc += __shfl_xor_sync(0xffffffffu, acc, o);
    if (lane == 0) logits[e] = acc + predB[0];
}

// ------------------- BCE loss -------------------
__global__ void loss_kernel(const float* __restrict__ logits, const float* __restrict__ labels,
                            float* __restrict__ out) {
    __shared__ float sh[256];
    int tid = threadIdx.x;
    float s = 0.f;
    for (int e = tid; e < E_EDGES; e += 256) {
        float l = logits[e], y = labels[e];
        s += fmaxf(l, 0.f) - l * y + log1pf(expf(-fabsf(l)));
    }
    sh[tid] = s;
    __syncthreads();
    for (int st = 128; st >= 1; st >>= 1) {
        if (tid < st) sh[tid] += sh[tid + st];
        __syncthreads();
    }
    if (tid == 0) out[0] = sh[0] / (float)E_EDGES;
}

// ------------------- streams/events -------------------
struct StreamPack {
    cudaStream_t s2 = nullptr, s3 = nullptr;
    cudaEvent_t evRoot = nullptr, evGCN = nullptr, evP1 = nullptr;
    bool ok = false;
    StreamPack() {
        if (cudaStreamCreateWithFlags(&s2, cudaStreamNonBlocking) != cudaSuccess) return;
        if (cudaStreamCreateWithFlags(&s3, cudaStreamNonBlocking) != cudaSuccess) return;
        if (cudaEventCreateWithFlags(&evRoot, cudaEventDisableTiming) != cudaSuccess) return;
        if (cudaEventCreateWithFlags(&evGCN, cudaEventDisableTiming) != cudaSuccess) return;
        if (cudaEventCreateWithFlags(&evP1, cudaEventDisableTiming) != cudaSuccess) return;
        ok = true;
    }
};
static StreamPack g_sp;

// ------------------- launch -------------------
extern "C" void kernel_launch(void* const* d_in, const int* in_sizes, int n_in,
                              void* d_out, int out_size) {
    const int*   src    = (const int*)d_in[0];
    const int*   dst    = (const int*)d_in[1];
    const float* labels = (const float*)d_in[2];
    const float* adj    = (const float*)d_in[3];
    const float* x      = (const float*)d_in[4];
    const float* Wg1    = (const float*)d_in[5];
    const float* Wg2    = (const float*)d_in[6];
    const float* Wp1    = (const float*)d_in[7];
    const float* b1     = (const float*)d_in[8];
    const float* Ws1    = (const float*)d_in[9];
    const float* Wp2    = (const float*)d_in[10];
    const float* b2     = (const float*)d_in[11];
    const float* Ws2    = (const float*)d_in[12];
    const float* PredW  = (const float*)d_in[13];
    const float* PredB  = (const float*)d_in[14];
    float* out = (float*)d_out;

    float *bufA, *bufB, *bufD, *bufE, *bufF, *gg;
    cudaGetSymbolAddress((void**)&bufA, g_bufA);
    cudaGetSymbolAddress((void**)&bufB, g_bufB);
    cudaGetSymbolAddress((void**)&bufD, g_bufD);
    cudaGetSymbolAddress((void**)&bufE, g_bufE);
    cudaGetSymbolAddress((void**)&bufF, g_bufF);
    cudaGetSymbolAddress((void**)&gg,   g_g);

    cudaFuncSetAttribute(simgemm_mma, cudaFuncAttributeMaxDynamicSharedMemorySize, SIM_SMEM);
    cudaFuncSetAttribute(gemm_t4<128, 128>, cudaFuncAttributeMaxDynamicSharedMemorySize, G4_128_128);
    cudaFuncSetAttribute(gemm_t4<128, 256>, cudaFuncAttributeMaxDynamicSharedMemorySize, G4_128_256);
    cudaFuncSetAttribute(sage_fused, cudaFuncAttributeMaxDynamicSharedMemorySize, SAGE_SMEM);

    bool forked = g_sp.ok;
    cudaStream_t s2 = forked ? g_sp.s2 : (cudaStream_t)0;
    cudaStream_t s3 = forked ? g_sp.s3 : (cudaStream_t)0;

    if (forked) {
        cudaEventRecord(g_sp.evRoot, 0);
        cudaStreamWaitEvent(s2, g_sp.evRoot, 0);
        cudaStreamWaitEvent(s3, g_sp.evRoot, 0);
    }

    // --- side stream s2: adjacency + GCN branch -> bufB, then head half g = h1 @ PredW_top ---
    zero_colcnt<<<N / 256, 256, 0, s2>>>();
    build_csr<<<N / 8, 256, 0, s2>>>(adj);
    colcnt_to_isc<<<N / 256, 256, 0, s2>>>();
    gemm_t4<128, 128><<<N / 16, 256, G4_128_128, s2>>>(x,    nullptr, Wg1, nullptr, 0, 0, bufA);
    gcn_spmm<<<N, 128, 0, s2>>>(bufA, bufB);
    gemm_t4<128, 128><<<N / 16, 256, G4_128_128, s2>>>(bufB, nullptr, Wg2, nullptr, 0, 0, bufA);
    gcn_spmm<<<N, 128, 0, s2>>>(bufA, bufB);
    gemm_t4<128, 256><<<N / 16, 512, G4_128_256, s2>>>(bufB, nullptr, PredW, nullptr, 0, 0, gg);
    if (forked) cudaEventRecord(g_sp.evGCN, s2);

    // --- side stream s3: SAGE layer-1 projection -> bufE ---
    gemm_t4<128, 128><<<N / 16, 256, G4_128_128, s3>>>(x, nullptr, Wp1, b1, 1, 0, bufE);
    if (forked) cudaEventRecord(g_sp.evP1, s3);

    // --- main stream: sim graph ---
    norm_split<<<N / 8, 256>>>(x);
    simgemm_mma<<<2352, 256, SIM_SMEM>>>();
    topk_kernel<<<N, 256>>>();

    if (forked) cudaStreamWaitEvent(0, g_sp.evP1, 0);
    // --- SAGE branch (fused agg+gemm) -> bufF ---
    sage_fused<<<N / 16, 256, SAGE_SMEM>>>(x, bufE, Ws1, bufD);
    gemm_t4<128, 128><<<N / 16, 256, G4_128_128>>>(bufD, nullptr, Wp2, b2, 1, 0, bufE);
    sage_fused<<<N / 16, 256, SAGE_SMEM>>>(bufD, bufE, Ws2, bufF);

    if (forked) cudaStreamWaitEvent(0, g_sp.evGCN, 0);
    // --- head second half: g += h2 @ PredW_bottom ---
    gemm_t4<128, 256><<<N / 16, 512, G4_128_256>>>(bufF, nullptr, PredW + 128 * 256, nullptr, 0, 1, gg);
    edge_kernel<<<(E_EDGES * 32) / 256, 256>>>(src, dst, gg, bufB, bufF, PredB, out + 1);
    loss_kernel<<<1, 256>>>(out + 1, labels, out);
}

// round 16
// speedup vs baseline: 1.0166x; 1.0166x over previous
#include <cuda_runtime.h>
#include <cuda_bf16.h>
#include <math.h>
#include <stdint.h>

#define N 6144
#define F 128
#define H 128
#define E_EDGES 16384
#define TOPK 32
#define MAXNNZ 96

// ------------------- device scratch -------------------
__device__ float g_nbr_val[N * MAXNNZ];
__device__ int   g_nbr_idx[N * MAXNNZ];
__device__ int   g_nnz[N];
__device__ float g_isr[N];
__device__ float g_isc[N];
__device__ int   g_colcnt[N];
__device__ float g_sim[(size_t)N * N];
__device__ __nv_bfloat16 g_xhib[N * F];
__device__ __nv_bfloat16 g_xlob[N * F];
__device__ float g_tkw[N * TOPK];
__device__ int   g_tki[N * TOPK];
__device__ float g_bufA[N * H];
__device__ float g_bufB[N * H];
__device__ float g_bufD[N * H];
__device__ float g_bufE[N * H];
__device__ float g_bufF[N * H];
__device__ float g_g[N * 2 * H];

__device__ __forceinline__ uint32_t smem_u32(const void* p) {
    uint32_t a;
    asm("{ .reg .u64 t; cvta.to.shared.u64 t, %1; cvt.u32.u64 %0, t; }" : "=r"(a) : "l"(p));
    return a;
}
__device__ __forceinline__ void cp16(uint32_t s, const float* g) {
    asm volatile("cp.async.cg.shared.global [%0], [%1], 16;" :: "r"(s), "l"(g));
}
#define CP_COMMIT() asm volatile("cp.async.commit_group;")
#define CP_WAIT2()  asm volatile("cp.async.wait_group 2;")

#define LDMX4(r, addr) \
    asm volatile("ldmatrix.sync.aligned.m8n8.x4.shared.b16 {%0,%1,%2,%3}, [%4];" \
        : "=r"((r)[0]), "=r"((r)[1]), "=r"((r)[2]), "=r"((r)[3]) : "r"(addr))

#define MMA_BF16(c, a, b0, b1) \
    asm volatile("mma.sync.aligned.m16n8k16.row.col.f32.bf16.bf16.f32 " \
        "{%0,%1,%2,%3}, {%4,%5,%6,%7}, {%8,%9}, {%0,%1,%2,%3};" \
        : "+f"((c)[0]), "+f"((c)[1]), "+f"((c)[2]), "+f"((c)[3]) \
        : "r"((a)[0]), "r"((a)[1]), "r"((a)[2]), "r"((a)[3]), "r"(b0), "r"(b1))

// ------------------- adj: CSR + row sums + col counts -------------------
__global__ void zero_colcnt() {
    int j = blockIdx.x * blockDim.x + threadIdx.x;
    if (j < N) g_colcnt[j] = 0;
}

__global__ void build_csr(const float* __restrict__ adj) {
    int row  = blockIdx.x * (blockDim.x >> 5) + (threadIdx.x >> 5);
    int lane = threadIdx.x & 31;
    if (row >= N) return;
    const float* arow = adj + (size_t)row * N;
    float s = 0.f;
    int base = 0;
    for (int c = 0; c < N; c += 32) {
        float v = arow[c + lane];
        s += v;
        unsigned b = __ballot_sync(0xffffffffu, v != 0.f);
        if (v != 0.f) {
            int pos = base + __popc(b & ((1u << lane) - 1u));
            if (pos < MAXNNZ) {
                g_nbr_idx[row * MAXNNZ + pos] = c + lane;
                g_nbr_val[row * MAXNNZ + pos] = v;
            }
            atomicAdd(&g_colcnt[c + lane], 1);
        }
        base += __popc(b);
    }
    for (int o = 16; o; o >>= 1) s += __shfl_xor_sync(0xffffffffu, s, o);
    if (lane == 0) {
        g_nnz[row] = base < MAXNNZ ? base : MAXNNZ;
        g_isr[row] = 1.f / sqrtf(s + 1.f);
    }
}

__global__ void colcnt_to_isc() {
    int j = blockIdx.x * blockDim.x + threadIdx.x;
    if (j < N) g_isc[j] = 1.f / sqrtf((float)g_colcnt[j] + 1.f);
}

// ------------------- fused row norms + NORMALIZE + bf16 hi/lo split -------------------
__global__ void norm_split(const float* __restrict__ x) {
    int row  = blockIdx.x * (blockDim.x >> 5) + (threadIdx.x >> 5);
    int lane = threadIdx.x & 31;
    if (row >= N) return;
    float v[4];
    float s = 0.f;
#pragma unroll
    for (int u = 0; u < 4; u++) {
        v[u] = x[(size_t)row * F + lane + 32 * u];
        s += v[u] * v[u];
    }
    for (int o = 16; o; o >>= 1) s += __shfl_xor_sync(0xffffffffu, s, o);
    float inv = 1.f / sqrtf(s);
#pragma unroll
    for (int u = 0; u < 4; u++) {
        size_t i = (size_t)row * F + lane + 32 * u;
        float xn = v[u] * inv;
        __nv_bfloat16 hi = __float2bfloat16(xn);
        g_xhib[i] = hi;
        g_xlob[i] = __float2bfloat16(xn - __bfloat162float(hi));
    }
}

// ------------------- sim GEMM (128x64 tiles, fused 3-term k-loop) -------------------
#define RS 136
#define OFF_AHI 0
#define OFF_ALO (OFF_AHI + 128 * RS * 2)
#define OFF_BHI (OFF_ALO + 128 * RS * 2)
#define OFF_BLO (OFF_BHI + 64 * RS * 2)
#define SIM_SMEM (OFF_BLO + 64 * RS * 2)

__global__ void __launch_bounds__(256, 2) simgemm_mma() {
    extern __shared__ char sm[];
    uint32_t sb = smem_u32(sm);
    int tid = threadIdx.x;
    int wid = tid >> 5, lane = tid & 31;

    int blk = blockIdx.x, bi = 0;
    while (blk >= 96 - 2 * bi) { blk -= 96 - 2 * bi; bi++; }
    int bj = 2 * bi + blk;
    int i0 = bi * 128, j0 = bj * 64;
    bool do_mirror = (bj >= 2 * bi + 2);

    {
        const uint4* shi = (const uint4*)g_xhib;
        const uint4* slo = (const uint4*)g_xlob;
        for (int idx = tid; idx < 128 * 16; idx += 256) {
            int r = idx >> 4, c = idx & 15;
            size_t gi = (size_t)(i0 + r) * 16 + c;
            uint32_t o = (uint32_t)(r * (RS * 2) + c * 16);
            *(uint4*)(sm + OFF_AHI + o) = shi[gi];
            *(uint4*)(sm + OFF_ALO + o) = slo[gi];
        }
        for (int idx = tid; idx < 64 * 16; idx += 256) {
            int r = idx >> 4, c = idx & 15;
            size_t gi = (size_t)(j0 + r) * 16 + c;
            uint32_t o = (uint32_t)(r * (RS * 2) + c * 16);
            *(uint4*)(sm + OFF_BHI + o) = shi[gi];
            *(uint4*)(sm + OFF_BLO + o) = slo[gi];
        }
    }
    __syncthreads();

    int wr = wid >> 1, wc = wid & 1;
    float acc[2][4][4];
#pragma unroll
    for (int mi = 0; mi < 2; mi++)
#pragma unroll
        for (int nj = 0; nj < 4; nj++)
#pragma unroll
            for (int q = 0; q < 4; q++) acc[mi][nj][q] = 0.f;

    uint32_t aoff = (uint32_t)((wr * 32 + (lane & 15)) * (RS * 2) + ((lane >> 4) << 4));
    uint32_t boff = (uint32_t)((wc * 32 + ((lane >> 4) << 3) + (lane & 7)) * (RS * 2)
                               + (((lane >> 3) & 1) << 4));
    uint32_t aHi = sb + OFF_AHI + aoff, aLo = sb + OFF_ALO + aoff;
    uint32_t bHi = sb + OFF_BHI + boff, bLo = sb + OFF_BLO + boff;

#pragma unroll
    for (int kk = 0; kk < 8; kk++) {
        uint32_t arh[2][4], arl[2][4], brh[2][4], brl[2][4];
        LDMX4(arh[0], aHi + kk * 32);
        LDMX4(arh[1], aHi + 16 * (RS * 2) + kk * 32);
        LDMX4(brh[0], bHi + kk * 32);
        LDMX4(brh[1], bHi + 16 * (RS * 2) + kk * 32);
        LDMX4(arl[0], aLo + kk * 32);
        LDMX4(arl[1], aLo + 16 * (RS * 2) + kk * 32);
        LDMX4(brl[0], bLo + kk * 32);
        LDMX4(brl[1], bLo + 16 * (RS * 2) + kk * 32);
#pragma unroll
        for (int mi = 0; mi < 2; mi++) {
            MMA_BF16(acc[mi][0], arh[mi], brh[0][0], brh[0][1]);
            MMA_BF16(acc[mi][1], arh[mi], brh[0][2], brh[0][3]);
            MMA_BF16(acc[mi][2], arh[mi], brh[1][0], brh[1][1]);
            MMA_BF16(acc[mi][3], arh[mi], brh[1][2], brh[1][3]);
            MMA_BF16(acc[mi][0], arh[mi], brl[0][0], brl[0][1]);
            MMA_BF16(acc[mi][1], arh[mi], brl[0][2], brl[0][3]);
            MMA_BF16(acc[mi][2], arh[mi], brl[1][0], brl[1][1]);
            MMA_BF16(acc[mi][3], arh[mi], brl[1][2], brl[1][3]);
            MMA_BF16(acc[mi][0], arl[mi], brh[0][0], brh[0][1]);
            MMA_BF16(acc[mi][1], arl[mi], brh[0][2], brh[0][3]);
            MMA_BF16(acc[mi][2], arl[mi], brh[1][0], brh[1][1]);
            MMA_BF16(acc[mi][3], arl[mi], brh[1][2], brh[1][3]);
        }
    }
    __syncthreads();

    float* Cs = (float*)(sm + OFF_AHI);  // 128 x 65
    {
        int rbase = wr * 32 + (lane >> 2);
        int cbase = wc * 32 + ((lane & 3) << 1);
#pragma unroll
        for (int mi = 0; mi < 2; mi++) {
            int r = rbase + mi * 16;
#pragma unroll
            for (int nj = 0; nj < 4; nj++) {
                int c = cbase + nj * 8;
                Cs[r * 65 + c]           = acc[mi][nj][0];
                Cs[r * 65 + c + 1]       = acc[mi][nj][1];
                Cs[(r + 8) * 65 + c]     = acc[mi][nj][2];
                Cs[(r + 8) * 65 + c + 1] = acc[mi][nj][3];
            }
        }
    }
    __syncthreads();

#pragma unroll
    for (int k = 0; k < 32; k++) {
        int idx = tid + k * 256;
        int r = idx >> 6, c = idx & 63;
        g_sim[(size_t)(i0 + r) * N + (j0 + c)] = Cs[r * 65 + c];
    }
    if (do_mirror) {
#pragma unroll
        for (int k = 0; k < 32; k++) {
            int idx = tid + k * 256;
            int rr = idx >> 7, cc = idx & 127;
            g_sim[(size_t)(j0 + rr) * N + (i0 + cc)] = Cs[cc * 65 + rr];
        }
    }
}

// ------------------- top-k v3: 3-level 2048-bin radix select -------------------
__device__ __forceinline__ unsigned f2key(float v) {
    unsigned u = __float_as_uint(v);
    return (u & 0x80000000u) ? ~u : (u | 0x80000000u);
}
__device__ __forceinline__ float key2f(unsigned k) {
    unsigned u = (k & 0x80000000u) ? (k & 0x7FFFFFFFu) : ~k;
    return __uint_as_float(u);
}

template<int NB>
__device__ __forceinline__ void find_cross(const int* hist, int* wsum, int nd,
                                           int tid, int lane, int wid,
                                           int* s_bin, int* s_need) {
    const int PER = NB / 256;
    int base = tid * PER;
    int h[PER];
    int lsum = 0;
#pragma unroll
    for (int j = 0; j < PER; j++) { h[j] = hist[base + j]; lsum += h[j]; }
    int v = lsum;
#pragma unroll
    for (int d = 1; d < 32; d <<= 1) {
        int n = __shfl_up_sync(0xffffffffu, v, d);
        if (lane >= d) v += n;
    }
    if (lane == 31) wsum[wid] = v;
    __syncthreads();
    if (tid < 8) {
        int w = wsum[tid];
#pragma unroll
        for (int d = 1; d < 8; d <<= 1) {
            int n = __shfl_up_sync(0xffu, w, d);
            if (tid >= d) w += n;
        }
        wsum[tid] = w;
    }
    __syncthreads();
    int incl = v + (wid ? wsum[wid - 1] : 0);
    int total = wsum[7];
    int S = total - incl;
#pragma unroll
    for (int j = PER - 1; j >= 0; j--) {
        S += h[j];
        if (S >= nd && S - h[j] < nd) {
            *s_bin = base + j;
            *s_need = nd - (S - h[j]);
        }
    }
}

__global__ void __launch_bounds__(256) topk_kernel() {
    __shared__ unsigned keys[N];
    __shared__ int hist[2048];
    __shared__ int wsum[8];
    __shared__ float outv[TOPK];
    __shared__ int   outi[TOPK];
    __shared__ int s_bin, s_need;
    __shared__ float s_invd;

    int row = blockIdx.x, tid = threadIdx.x;
    int lane = tid & 31, wid = tid >> 5;
    const float* sr = g_sim + (size_t)row * N;
    const int CH = N / 256;

    for (int i = tid; i < 2048; i += 256) hist[i] = 0;
    __syncthreads();
    for (int i = tid; i < N; i += 256) {
        float v = sr[i];
        unsigned k = f2key(v);
        if (i == row) k = 0u;
        keys[i] = k;
        atomicAdd(&hist[k >> 21], 1);
    }
    __syncthreads();
    find_cross<2048>(hist, wsum, TOPK, tid, lane, wid, &s_bin, &s_need);
    __syncthreads();
    unsigned b1 = (unsigned)s_bin;
    int nd2 = s_need;
    __syncthreads();

    for (int i = tid; i < 2048; i += 256) hist[i] = 0;
    __syncthreads();
#pragma unroll
    for (int e = 0; e < CH; e++) {
        unsigned k = keys[e * 256 + tid];
        if ((k >> 21) == b1) atomicAdd(&hist[(k >> 10) & 0x7FFu], 1);
    }
    __syncthreads();
    find_cross<2048>(hist, wsum, nd2, tid, lane, wid, &s_bin, &s_need);
    __syncthreads();
    unsigned pre21 = (b1 << 11) | (unsigned)s_bin;
    int nd3 = s_need;
    __syncthreads();

    for (int i = tid; i < 1024; i += 256) hist[i] = 0;
    __syncthreads();
#pragma unroll
    for (int e = 0; e < CH; e++) {
        unsigned k = keys[e * 256 + tid];
        if ((k >> 10) == pre21) atomicAdd(&hist[k & 0x3FFu], 1);
    }
    __syncthreads();
    find_cross<1024>(hist, wsum, nd3, tid, lane, wid, &s_bin, &s_need);
    __syncthreads();
    unsigned T = (pre21 << 10) | (unsigned)s_bin;
    int need_eq = s_need;
    __syncthreads();

    int cg = 0, ce = 0;
#pragma unroll
    for (int e = 0; e < CH; e++) {
        unsigned k = keys[e * 256 + tid];
        cg += (k > T);
        ce += (k == T);
    }
    {
        int v = (cg << 16) | ce;
#pragma unroll
        for (int d = 1; d < 32; d <<= 1) {
            int n = __shfl_up_sync(0xffffffffu, v, d);
            if (lane >= d) v += n;
        }
        if (lane == 31) wsum[wid] = v;
        __syncthreads();
        if (tid < 8) {
            int w = wsum[tid];
#pragma unroll
            for (int d = 1; d < 8; d <<= 1) {
                int n = __shfl_up_sync(0xffu, w, d);
                if (tid >= d) w += n;
            }
            wsum[tid] = w;
        }
        __syncthreads();
        int incl = v + (wid ? wsum[wid - 1] : 0);
        int total = wsum[7];
        int total_g = total >> 16;
        int pg = (incl >> 16) - cg;
        int pe = total_g + ((incl & 0xFFFF) - ce);
#pragma unroll
        for (int e = 0; e < CH; e++) {
            int gi = e * 256 + tid;
            unsigned k = keys[gi];
            if (k > T) {
                outv[pg] = key2f(k); outi[pg] = gi; pg++;
            } else if (k == T) {
                if (pe < total_g + need_eq) { outv[pe] = key2f(k); outi[pe] = gi; }
                pe++;
            }
        }
    }
    __syncthreads();
    if (tid < 32) {
        float s = outv[tid];
        for (int o = 16; o; o >>= 1) s += __shfl_xor_sync(0xffffffffu, s, o);
        if (tid == 0) s_invd = 1.f / fmaxf(s, 1e-5f);
    }
    __syncthreads();
    if (tid < TOPK) {
        g_tkw[row * TOPK + tid] = outv[tid] * s_invd;
        g_tki[row * TOPK + tid] = outi[tid];
    }
}

// ------------------- gemm v4: 2*HOUT threads, RPB=16, 4-buffer cp.async ring -------------------
template<int K, int HOUT>
__global__ void __launch_bounds__(2 * HOUT) gemm_t4(const float* __restrict__ A1,
                                                    const float* __restrict__ A2,
                                                    const float* __restrict__ W,
                                                    const float* __restrict__ bias, int act,
                                                    int accum,
                                                    float* __restrict__ C) {
    const int RPB = 16;
    const int BLK = 2 * HOUT;
    const int CHK = 2048 / HOUT;
    const int NCH = K / CHK;
    const int CBYTES = CHK * HOUT * 4;
    extern __shared__ float dyn[];
    float* wring = dyn;
    float* a_sh  = dyn + 4 * CHK * HOUT;
    uint32_t wsm = smem_u32(wring);

    int tid = threadIdx.x;
    int f  = tid & (HOUT - 1);
    int rh = tid / HOUT;
    int r0 = blockIdx.x * RPB;
    int rbase = rh * 8;

#pragma unroll
    for (int c = 0; c < 2; c++) {
        const float* gW = W + (size_t)c * CHK * HOUT;
        uint32_t dst = wsm + c * CBYTES;
        for (int i = tid; i < CHK * HOUT / 4; i += BLK)
            cp16(dst + (uint32_t)i * 16, gW + (size_t)i * 4);
        CP_COMMIT();
    }

    if (K == 256) {
        for (int idx = tid; idx < RPB * 128; idx += BLK) {
            int r = idx >> 7, k = idx & 127;
            a_sh[r * K + k]       = A1[(size_t)(r0 + r) * 128 + k];
            a_sh[r * K + 128 + k] = A2[(size_t)(r0 + r) * 128 + k];
        }
    } else {
        for (int idx = tid; idx < RPB * K; idx += BLK) {
            int r = idx / K, k = idx & (K - 1);
            a_sh[r * K + k] = A1[(size_t)(r0 + r) * K + k];
        }
    }

    float acc[8];
    if (accum) {
#pragma unroll
        for (int r = 0; r < 8; r++) acc[r] = C[(size_t)(r0 + rbase + r) * HOUT + f];
    } else {
        float b = bias ? bias[f] : 0.f;
#pragma unroll
        for (int r = 0; r < 8; r++) acc[r] = b;
    }

#pragma unroll
    for (int ch = 0; ch < NCH; ch++) {
        if (ch + 2 < NCH) {
            const float* gW = W + (size_t)(ch + 2) * CHK * HOUT;
            uint32_t dst = wsm + ((ch + 2) & 3) * CBYTES;
            for (int i = tid; i < CHK * HOUT / 4; i += BLK)
                cp16(dst + (uint32_t)i * 16, gW + (size_t)i * 4);
        }
        CP_COMMIT();
        CP_WAIT2();
        __syncthreads();

        const float* wp = wring + (ch & 3) * CHK * HOUT;
        int kc = ch * CHK;
#pragma unroll
        for (int kk = 0; kk < CHK; kk += 4) {
            float w0 = wp[kk * HOUT + f];
            float w1 = wp[(kk + 1) * HOUT + f];
            float w2 = wp[(kk + 2) * HOUT + f];
            float w3 = wp[(kk + 3) * HOUT + f];
#pragma unroll
            for (int r = 0; r < 8; r++) {
                float4 av = *(const float4*)&a_sh[(rbase + r) * K + kc + kk];
                acc[r] += av.x * w0 + av.y * w1 + av.z * w2 + av.w * w3;
            }
        }
    }

#pragma unroll
    for (int r = 0; r < 8; r++) {
        float v = acc[r];
        if (act) v = v > 0.f ? v : expm1f(v);
        C[(size_t)(r0 + rbase + r) * HOUT + f] = v;
    }
}

#define G4_128_128 ((4 * 16 * 128 + 16 * 128) * 4)
#define G4_128_256 ((4 * 8 * 256 + 16 * 128) * 4)

// ------------------- fused SAGE: 256 threads, RPB=16 -------------------
__global__ void __launch_bounds__(256) sage_fused(const float* __restrict__ z,
                                                  const float* __restrict__ h,
                                                  const float* __restrict__ W,
                                                  float* __restrict__ C) {
    const int RPB = 16, K = 256, HOUT = 128, BLK = 256;
    const int CHK = 16, NCH = 16;
    const int CBYTES = CHK * HOUT * 4;
    extern __shared__ float dyn[];
    float* wring = dyn;
    float* a_sh  = dyn + 4 * CHK * HOUT;
    float* twv   = a_sh + RPB * K;
    int*   twi   = (int*)(twv + RPB * TOPK);
    uint32_t wsm = smem_u32(wring);

    int tid = threadIdx.x;
    int f  = tid & 127;
    int rh = tid >> 7;
    int r0 = blockIdx.x * RPB;
    int rbase = rh * 8;

#pragma unroll
    for (int c = 0; c < 2; c++) {
        const float* gW = W + (size_t)c * CHK * HOUT;
        uint32_t dst = wsm + c * CBYTES;
        for (int i = tid; i < CHK * HOUT / 4; i += BLK)
            cp16(dst + (uint32_t)i * 16, gW + (size_t)i * 4);
        CP_COMMIT();
    }

    for (int i = tid; i < RPB * TOPK; i += BLK) {
        twv[i] = g_tkw[r0 * TOPK + i];
        twi[i] = g_tki[r0 * TOPK + i];
    }
#pragma unroll
    for (int r = 0; r < 8; r++)
        a_sh[(rbase + r) * K + f] = z[(size_t)(r0 + rbase + r) * 128 + f];
    __syncthreads();

#pragma unroll
    for (int r = 0; r < 8; r++) {
        int rr = rbase + r;
        float acc = 0.f;
#pragma unroll 8
        for (int q = 0; q < TOPK; q++)
            acc += twv[rr * TOPK + q] * h[(size_t)twi[rr * TOPK + q] * 128 + f];
        a_sh[rr * K + 128 + f] = acc;
    }

    float acc[8];
#pragma unroll
    for (int r = 0; r < 8; r++) acc[r] = 0.f;

#pragma unroll
    for (int ch = 0; ch < NCH; ch++) {
        if (ch + 2 < NCH) {
            const float* gW = W + (size_t)(ch + 2) * CHK * HOUT;
            uint32_t dst = wsm + ((ch + 2) & 3) * CBYTES;
            for (int i = tid; i < CHK * HOUT / 4; i += BLK)
                cp16(dst + (uint32_t)i * 16, gW + (size_t)i * 4);
        }
        CP_COMMIT();
        CP_WAIT2();
        __syncthreads();

        const float* wp = wring + (ch & 3) * CHK * HOUT;
        int kc = ch * CHK;
#pragma unroll
        for (int kk = 0; kk < CHK; kk += 4) {
            float w0 = wp[kk * HOUT + f];
            float w1 = wp[(kk + 1) * HOUT + f];
            float w2 = wp[(kk + 2) * HOUT + f];
            float w3 = wp[(kk + 3) * HOUT + f];
#pragma unroll
            for (int r = 0; r < 8; r++) {
                float4 av = *(const float4*)&a_sh[(rbase + r) * K + kc + kk];
                acc[r] += av.x * w0 + av.y * w1 + av.z * w2 + av.w * w3;
            }
        }
    }

#pragma unroll
    for (int r = 0; r < 8; r++) {
        float v = acc[r];
        v = v > 0.f ? v : expm1f(v);
        C[(size_t)(r0 + rbase + r) * HOUT + f] = v;
    }
}
#define SAGE_SMEM ((4 * 16 * 128 + 16 * 256 + 2 * 16 * 32) * 4)

// ------------------- GCN SpMM -------------------
__global__ void gcn_spmm(const float* __restrict__ zw, float* __restrict__ out) {
    int row = blockIdx.x, f = threadIdx.x;
    __shared__ float vv[MAXNNZ];
    __shared__ int   vi[MAXNNZ];
    int nnz = g_nnz[row];
    for (int i = f; i < nnz; i += H) {
        int j = g_nbr_idx[row * MAXNNZ + i];
        vi[i] = j;
        vv[i] = g_nbr_val[row * MAXNNZ + i] * g_isc[j];
    }
    __syncthreads();
    float acc = g_isc[row] * zw[(size_t)row * H + f];
    for (int i = 0; i < nnz; i++) acc += vv[i] * zw[(size_t)vi[i] * H + f];
    float v = acc * g_isr[row];
    out[(size_t)row * H + f] = v > 0.f ? v : expm1f(v);
}

// ------------------- edge logits -------------------
__global__ void edge_kernel(const int* __restrict__ src, const int* __restrict__ dst,
                            const float* __restrict__ g, const float* __restrict__ h1,
                            const float* __restrict__ h2, const float* __restrict__ predB,
                            float* __restrict__ logits) {
    int e = (blockIdx.x * blockDim.x + threadIdx.x) >> 5;
    int lane = threadIdx.x & 31;
    if (e >= E_EDGES) return;
    int s = src[e], d = dst[e];
    const float* gr = g + (size_t)s * (2 * H);
    float acc = 0.f;
#pragma unroll
    for (int u = 0; u < 8; u++) {
        int c = lane + 32 * u;
        float hv = (c < H) ? h1[(size_t)d * H + c] : h2[(size_t)d * H + (c - H)];
        acc += gr[c] * hv;
    }
    for (int o = 16; o; o >>= 1) acc += __shfl_xor_sync(0xffffffffu, acc, o);
    if (lane == 0) logits[e] = acc + predB[0];
}

// ------------------- BCE loss -------------------
__global__ void loss_kernel(const float* __restrict__ logits, const float* __restrict__ labels,
                            float* __restrict__ out) {
    __shared__ float sh[256];
    int tid = threadIdx.x;
    float s = 0.f;
    for (int e = tid; e < E_EDGES; e += 256) {
        float l = logits[e], y = labels[e];
        s += fmaxf(l, 0.f) - l * y + log1pf(expf(-fabsf(l)));
    }
    sh[tid] = s;
    __syncthreads();
    for (int st = 128; st >= 1; st >>= 1) {
        if (tid < st) sh[tid] += sh[tid + st];
        __syncthreads();
    }
    if (tid == 0) out[0] = sh[0] / (float)E_EDGES;
}

// ------------------- streams/events -------------------
struct StreamPack {
    cudaStream_t s2 = nullptr, s3 = nullptr;
    cudaEvent_t evRoot = nullptr, evGCN = nullptr, evP1 = nullptr;
    bool ok = false;
    StreamPack() {
        if (cudaStreamCreateWithFlags(&s2, cudaStreamNonBlocking) != cudaSuccess) return;
        if (cudaStreamCreateWithFlags(&s3, cudaStreamNonBlocking) != cudaSuccess) return;
        if (cudaEventCreateWithFlags(&evRoot, cudaEventDisableTiming) != cudaSuccess) return;
        if (cudaEventCreateWithFlags(&evGCN, cudaEventDisableTiming) != cudaSuccess) return;
        if (cudaEventCreateWithFlags(&evP1, cudaEventDisableTiming) != cudaSuccess) return;
        ok = true;
    }
};
static StreamPack g_sp;

// ------------------- launch -------------------
extern "C" void kernel_launch(void* const* d_in, const int* in_sizes, int n_in,
                              void* d_out, int out_size) {
    const int*   src    = (const int*)d_in[0];
    const int*   dst    = (const int*)d_in[1];
    const float* labels = (const float*)d_in[2];
    const float* adj    = (const float*)d_in[3];
    const float* x      = (const float*)d_in[4];
    const float* Wg1    = (const float*)d_in[5];
    const float* Wg2    = (const float*)d_in[6];
    const float* Wp1    = (const float*)d_in[7];
    const float* b1     = (const float*)d_in[8];
    const float* Ws1    = (const float*)d_in[9];
    const float* Wp2    = (const float*)d_in[10];
    const float* b2     = (const float*)d_in[11];
    const float* Ws2    = (const float*)d_in[12];
    const float* PredW  = (const float*)d_in[13];
    const float* PredB  = (const float*)d_in[14];
    float* out = (float*)d_out;

    float *bufA, *bufB, *bufD, *bufE, *bufF, *gg;
    cudaGetSymbolAddress((void**)&bufA, g_bufA);
    cudaGetSymbolAddress((void**)&bufB, g_bufB);
    cudaGetSymbolAddress((void**)&bufD, g_bufD);
    cudaGetSymbolAddress((void**)&bufE, g_bufE);
    cudaGetSymbolAddress((void**)&bufF, g_bufF);
    cudaGetSymbolAddress((void**)&gg,   g_g);

    cudaFuncSetAttribute(simgemm_mma, cudaFuncAttributeMaxDynamicSharedMemorySize, SIM_SMEM);
    cudaFuncSetAttribute(gemm_t4<128, 128>, cudaFuncAttributeMaxDynamicSharedMemorySize, G4_128_128);
    cudaFuncSetAttribute(gemm_t4<128, 256>, cudaFuncAttributeMaxDynamicSharedMemorySize, G4_128_256);
    cudaFuncSetAttribute(sage_fused, cudaFuncAttributeMaxDynamicSharedMemorySize, SAGE_SMEM);

    bool forked = g_sp.ok;
    cudaStream_t s2 = forked ? g_sp.s2 : (cudaStream_t)0;
    cudaStream_t s3 = forked ? g_sp.s3 : (cudaStream_t)0;

    if (forked) {
        cudaEventRecord(g_sp.evRoot, 0);
        cudaStreamWaitEvent(s2, g_sp.evRoot, 0);
        cudaStreamWaitEvent(s3, g_sp.evRoot, 0);
    }

    // --- side stream s2: adjacency + GCN branch -> bufB, then head half g = h1 @ PredW_top ---
    zero_colcnt<<<N / 256, 256, 0, s2>>>();
    build_csr<<<N / 8, 256, 0, s2>>>(adj);
    colcnt_to_isc<<<N / 256, 256, 0, s2>>>();
    gemm_t4<128, 128><<<N / 16, 256, G4_128_128, s2>>>(x,    nullptr, Wg1, nullptr, 0, 0, bufA);
    gcn_spmm<<<N, 128, 0, s2>>>(bufA, bufB);
    gemm_t4<128, 128><<<N / 16, 256, G4_128_128, s2>>>(bufB, nullptr, Wg2, nullptr, 0, 0, bufA);
    gcn_spmm<<<N, 128, 0, s2>>>(bufA, bufB);
    gemm_t4<128, 256><<<N / 16, 512, G4_128_256, s2>>>(bufB, nullptr, PredW, nullptr, 0, 0, gg);
    if (forked) cudaEventRecord(g_sp.evGCN, s2);

    // --- side stream s3: SAGE layer-1 projection -> bufE ---
    gemm_t4<128, 128><<<N / 16, 256, G4_128_128, s3>>>(x, nullptr, Wp1, b1, 1, 0, bufE);
    if (forked) cudaEventRecord(g_sp.evP1, s3);

    // --- main stream: sim graph ---
    norm_split<<<N / 8, 256>>>(x);
    simgemm_mma<<<2352, 256, SIM_SMEM>>>();
    topk_kernel<<<N, 256>>>();

    if (forked) cudaStreamWaitEvent(0, g_sp.evP1, 0);
    // --- SAGE branch (fused agg+gemm) -> bufF ---
    sage_fused<<<N / 16, 256, SAGE_SMEM>>>(x, bufE, Ws1, bufD);
    gemm_t4<128, 128><<<N / 16, 256, G4_128_128>>>(bufD, nullptr, Wp2, b2, 1, 0, bufE);
    sage_fused<<<N / 16, 256, SAGE_SMEM>>>(bufD, bufE, Ws2, bufF);

    if (forked) cudaStreamWaitEvent(0, g_sp.evGCN, 0);
    // --- head second half: g += h2 @ PredW_bottom ---
    gemm_t4<128, 256><<<N / 16, 512, G4_128_256>>>(bufF, nullptr, PredW + 128 * 256, nullptr, 0, 1, gg);
    edge_kernel<<<(E_EDGES * 32) / 256, 256>>>(src, dst, gg, bufB, bufF, PredB, out + 1);
    loss_kernel<<<1, 256>>>(out + 1, labels, out);
}

// round 17
// speedup vs baseline: 1.0454x; 1.0284x over previous
#include <cuda_runtime.h>
#include <cuda_bf16.h>
#include <math.h>
#include <stdint.h>

#define N 6144
#define F 128
#define H 128
#define E_EDGES 16384
#define TOPK 32
#define MAXNNZ 96

// ------------------- device scratch -------------------
__device__ float g_nbr_val[N * MAXNNZ];
__device__ int   g_nbr_idx[N * MAXNNZ];
__device__ int   g_nnz[N];
__device__ float g_isr[N];
__device__ float g_isc[N];
__device__ int   g_colcnt[N];
__device__ unsigned g_simk[(size_t)N * N];   // sim stored as order-preserving u32 keys
__device__ __nv_bfloat16 g_xhib[N * F];
__device__ __nv_bfloat16 g_xlob[N * F];
__device__ float g_tkw[N * TOPK];
__device__ int   g_tki[N * TOPK];
__device__ float g_bufA[N * H];
__device__ float g_bufB[N * H];
__device__ float g_bufD[N * H];
__device__ float g_bufE[N * H];
__device__ float g_bufF[N * H];
__device__ float g_g[N * 2 * H];

__device__ __forceinline__ uint32_t smem_u32(const void* p) {
    uint32_t a;
    asm("{ .reg .u64 t; cvta.to.shared.u64 t, %1; cvt.u32.u64 %0, t; }" : "=r"(a) : "l"(p));
    return a;
}
__device__ __forceinline__ void cp16(uint32_t s, const void* g) {
    asm volatile("cp.async.cg.shared.global [%0], [%1], 16;" :: "r"(s), "l"(g));
}
#define CP_COMMIT() asm volatile("cp.async.commit_group;")
#define CP_WAIT2()  asm volatile("cp.async.wait_group 2;")
#define CP_WAIT0()  asm volatile("cp.async.wait_group 0;")

#define LDMX4(r, addr) \
    asm volatile("ldmatrix.sync.aligned.m8n8.x4.shared.b16 {%0,%1,%2,%3}, [%4];" \
        : "=r"((r)[0]), "=r"((r)[1]), "=r"((r)[2]), "=r"((r)[3]) : "r"(addr))

#define MMA_BF16(c, a, b0, b1) \
    asm volatile("mma.sync.aligned.m16n8k16.row.col.f32.bf16.bf16.f32 " \
        "{%0,%1,%2,%3}, {%4,%5,%6,%7}, {%8,%9}, {%0,%1,%2,%3};" \
        : "+f"((c)[0]), "+f"((c)[1]), "+f"((c)[2]), "+f"((c)[3]) \
        : "r"((a)[0]), "r"((a)[1]), "r"((a)[2]), "r"((a)[3]), "r"(b0), "r"(b1))

// order-preserving float<->u32 key bijection
__device__ __forceinline__ unsigned f2key(float v) {
    unsigned u = __float_as_uint(v);
    return (u & 0x80000000u) ? ~u : (u | 0x80000000u);
}
__device__ __forceinline__ float key2f(unsigned k) {
    unsigned u = (k & 0x80000000u) ? (k & 0x7FFFFFFFu) : ~k;
    return __uint_as_float(u);
}

// ------------------- adj: CSR + row sums + col counts -------------------
__global__ void zero_colcnt() {
    int j = blockIdx.x * blockDim.x + threadIdx.x;
    if (j < N) g_colcnt[j] = 0;
}

__global__ void build_csr(const float* __restrict__ adj) {
    int row  = blockIdx.x * (blockDim.x >> 5) + (threadIdx.x >> 5);
    int lane = threadIdx.x & 31;
    if (row >= N) return;
    const float* arow = adj + (size_t)row * N;
    float s = 0.f;
    int base = 0;
    for (int c = 0; c < N; c += 32) {
        float v = arow[c + lane];
        s += v;
        unsigned b = __ballot_sync(0xffffffffu, v != 0.f);
        if (v != 0.f) {
            int pos = base + __popc(b & ((1u << lane) - 1u));
            if (pos < MAXNNZ) {
                g_nbr_idx[row * MAXNNZ + pos] = c + lane;
                g_nbr_val[row * MAXNNZ + pos] = v;
            }
            atomicAdd(&g_colcnt[c + lane], 1);
        }
        base += __popc(b);
    }
    for (int o = 16; o; o >>= 1) s += __shfl_xor_sync(0xffffffffu, s, o);
    if (lane == 0) {
        g_nnz[row] = base < MAXNNZ ? base : MAXNNZ;
        g_isr[row] = 1.f / sqrtf(s + 1.f);
    }
}

__global__ void colcnt_to_isc() {
    int j = blockIdx.x * blockDim.x + threadIdx.x;
    if (j < N) g_isc[j] = 1.f / sqrtf((float)g_colcnt[j] + 1.f);
}

// ------------------- fused row norms + NORMALIZE + bf16 hi/lo split -------------------
__global__ void norm_split(const float* __restrict__ x) {
    int row  = blockIdx.x * (blockDim.x >> 5) + (threadIdx.x >> 5);
    int lane = threadIdx.x & 31;
    if (row >= N) return;
    float v[4];
    float s = 0.f;
#pragma unroll
    for (int u = 0; u < 4; u++) {
        v[u] = x[(size_t)row * F + lane + 32 * u];
        s += v[u] * v[u];
    }
    for (int o = 16; o; o >>= 1) s += __shfl_xor_sync(0xffffffffu, s, o);
    float inv = 1.f / sqrtf(s);
#pragma unroll
    for (int u = 0; u < 4; u++) {
        size_t i = (size_t)row * F + lane + 32 * u;
        float xn = v[u] * inv;
        __nv_bfloat16 hi = __float2bfloat16(xn);
        g_xhib[i] = hi;
        g_xlob[i] = __float2bfloat16(xn - __bfloat162float(hi));
    }
}

// ------------------- sim GEMM (128x64 tiles, fused 3-term k-loop; stores u32 keys) -------------------
#define RS 136
#define OFF_AHI 0
#define OFF_ALO (OFF_AHI + 128 * RS * 2)
#define OFF_BHI (OFF_ALO + 128 * RS * 2)
#define OFF_BLO (OFF_BHI + 64 * RS * 2)
#define SIM_SMEM (OFF_BLO + 64 * RS * 2)

__global__ void __launch_bounds__(256, 2) simgemm_mma() {
    extern __shared__ char sm[];
    uint32_t sb = smem_u32(sm);
    int tid = threadIdx.x;
    int wid = tid >> 5, lane = tid & 31;

    int blk = blockIdx.x, bi = 0;
    while (blk >= 96 - 2 * bi) { blk -= 96 - 2 * bi; bi++; }
    int bj = 2 * bi + blk;
    int i0 = bi * 128, j0 = bj * 64;
    bool do_mirror = (bj >= 2 * bi + 2);

    {
        const uint4* shi = (const uint4*)g_xhib;
        const uint4* slo = (const uint4*)g_xlob;
        for (int idx = tid; idx < 128 * 16; idx += 256) {
            int r = idx >> 4, c = idx & 15;
            size_t gi = (size_t)(i0 + r) * 16 + c;
            uint32_t o = (uint32_t)(r * (RS * 2) + c * 16);
            *(uint4*)(sm + OFF_AHI + o) = shi[gi];
            *(uint4*)(sm + OFF_ALO + o) = slo[gi];
        }
        for (int idx = tid; idx < 64 * 16; idx += 256) {
            int r = idx >> 4, c = idx & 15;
            size_t gi = (size_t)(j0 + r) * 16 + c;
            uint32_t o = (uint32_t)(r * (RS * 2) + c * 16);
            *(uint4*)(sm + OFF_BHI + o) = shi[gi];
            *(uint4*)(sm + OFF_BLO + o) = slo[gi];
        }
    }
    __syncthreads();

    int wr = wid >> 1, wc = wid & 1;
    float acc[2][4][4];
#pragma unroll
    for (int mi = 0; mi < 2; mi++)
#pragma unroll
        for (int nj = 0; nj < 4; nj++)
#pragma unroll
            for (int q = 0; q < 4; q++) acc[mi][nj][q] = 0.f;

    uint32_t aoff = (uint32_t)((wr * 32 + (lane & 15)) * (RS * 2) + ((lane >> 4) << 4));
    uint32_t boff = (uint32_t)((wc * 32 + ((lane >> 4) << 3) + (lane & 7)) * (RS * 2)
                               + (((lane >> 3) & 1) << 4));
    uint32_t aHi = sb + OFF_AHI + aoff, aLo = sb + OFF_ALO + aoff;
    uint32_t bHi = sb + OFF_BHI + boff, bLo = sb + OFF_BLO + boff;

#pragma unroll
    for (int kk = 0; kk < 8; kk++) {
        uint32_t arh[2][4], arl[2][4], brh[2][4], brl[2][4];
        LDMX4(arh[0], aHi + kk * 32);
        LDMX4(arh[1], aHi + 16 * (RS * 2) + kk * 32);
        LDMX4(brh[0], bHi + kk * 32);
        LDMX4(brh[1], bHi + 16 * (RS * 2) + kk * 32);
        LDMX4(arl[0], aLo + kk * 32);
        LDMX4(arl[1], aLo + 16 * (RS * 2) + kk * 32);
        LDMX4(brl[0], bLo + kk * 32);
        LDMX4(brl[1], bLo + 16 * (RS * 2) + kk * 32);
#pragma unroll
        for (int mi = 0; mi < 2; mi++) {
            MMA_BF16(acc[mi][0], arh[mi], brh[0][0], brh[0][1]);
            MMA_BF16(acc[mi][1], arh[mi], brh[0][2], brh[0][3]);
            MMA_BF16(acc[mi][2], arh[mi], brh[1][0], brh[1][1]);
            MMA_BF16(acc[mi][3], arh[mi], brh[1][2], brh[1][3]);
            MMA_BF16(acc[mi][0], arh[mi], brl[0][0], brl[0][1]);
            MMA_BF16(acc[mi][1], arh[mi], brl[0][2], brl[0][3]);
            MMA_BF16(acc[mi][2], arh[mi], brl[1][0], brl[1][1]);
            MMA_BF16(acc[mi][3], arh[mi], brl[1][2], brl[1][3]);
            MMA_BF16(acc[mi][0], arl[mi], brh[0][0], brh[0][1]);
            MMA_BF16(acc[mi][1], arl[mi], brh[0][2], brh[0][3]);
            MMA_BF16(acc[mi][2], arl[mi], brh[1][0], brh[1][1]);
            MMA_BF16(acc[mi][3], arl[mi], brh[1][2], brh[1][3]);
        }
    }
    __syncthreads();

    float* Cs = (float*)(sm + OFF_AHI);  // 128 x 65
    {
        int rbase = wr * 32 + (lane >> 2);
        int cbase = wc * 32 + ((lane & 3) << 1);
#pragma unroll
        for (int mi = 0; mi < 2; mi++) {
            int r = rbase + mi * 16;
#pragma unroll
            for (int nj = 0; nj < 4; nj++) {
                int c = cbase + nj * 8;
                Cs[r * 65 + c]           = acc[mi][nj][0];
                Cs[r * 65 + c + 1]       = acc[mi][nj][1];
                Cs[(r + 8) * 65 + c]     = acc[mi][nj][2];
                Cs[(r + 8) * 65 + c + 1] = acc[mi][nj][3];
            }
        }
    }
    __syncthreads();

#pragma unroll
    for (int k = 0; k < 32; k++) {
        int idx = tid + k * 256;
        int r = idx >> 6, c = idx & 63;
        g_simk[(size_t)(i0 + r) * N + (j0 + c)] = f2key(Cs[r * 65 + c]);
    }
    if (do_mirror) {
#pragma unroll
        for (int k = 0; k < 32; k++) {
            int idx = tid + k * 256;
            int rr = idx >> 7, cc = idx & 127;
            g_simk[(size_t)(j0 + rr) * N + (i0 + cc)] = f2key(Cs[cc * 65 + rr]);
        }
    }
}

// ------------------- top-k v4: cp.async row load + 3-level 2048-bin radix select -------------------
template<int NB>
__device__ __forceinline__ void find_cross(const int* hist, int* wsum, int nd,
                                           int tid, int lane, int wid,
                                           int* s_bin, int* s_need) {
    const int PER = NB / 256;
    int base = tid * PER;
    int h[PER];
    int lsum = 0;
#pragma unroll
    for (int j = 0; j < PER; j++) { h[j] = hist[base + j]; lsum += h[j]; }
    int v = lsum;
#pragma unroll
    for (int d = 1; d < 32; d <<= 1) {
        int n = __shfl_up_sync(0xffffffffu, v, d);
        if (lane >= d) v += n;
    }
    if (lane == 31) wsum[wid] = v;
    __syncthreads();
    if (tid < 8) {
        int w = wsum[tid];
#pragma unroll
        for (int d = 1; d < 8; d <<= 1) {
            int n = __shfl_up_sync(0xffu, w, d);
            if (tid >= d) w += n;
        }
        wsum[tid] = w;
    }
    __syncthreads();
    int incl = v + (wid ? wsum[wid - 1] : 0);
    int total = wsum[7];
    int S = total - incl;
#pragma unroll
    for (int j = PER - 1; j >= 0; j--) {
        S += h[j];
        if (S >= nd && S - h[j] < nd) {
            *s_bin = base + j;
            *s_need = nd - (S - h[j]);
        }
    }
}

__global__ void __launch_bounds__(256) topk_kernel() {
    __shared__ unsigned keys[N];
    __shared__ int hist[2048];
    __shared__ int wsum[8];
    __shared__ float outv[TOPK];
    __shared__ int   outi[TOPK];
    __shared__ int s_bin, s_need;
    __shared__ float s_invd;

    int row = blockIdx.x, tid = threadIdx.x;
    int lane = tid & 31, wid = tid >> 5;
    const int CH = N / 256;

    // bulk async copy of the whole row into smem; zero hist while in flight
    {
        const uint4* sr4 = (const uint4*)(g_simk + (size_t)row * N);
        uint32_t kb = smem_u32(keys);
#pragma unroll
        for (int q = 0; q < 6; q++) {
            int i = q * 256 + tid;
            cp16(kb + (uint32_t)i * 16, sr4 + i);
        }
        CP_COMMIT();
    }
    for (int i = tid; i < 2048; i += 256) hist[i] = 0;
    CP_WAIT0();
    __syncthreads();
    if (tid == 0) keys[row] = 0u;   // mask self
    __syncthreads();

    // level-1 histogram from smem
#pragma unroll
    for (int e = 0; e < CH; e++) {
        unsigned k = keys[e * 256 + tid];
        atomicAdd(&hist[k >> 21], 1);
    }
    __syncthreads();
    find_cross<2048>(hist, wsum, TOPK, tid, lane, wid, &s_bin, &s_need);
    __syncthreads();
    unsigned b1 = (unsigned)s_bin;
    int nd2 = s_need;
    __syncthreads();

    for (int i = tid; i < 2048; i += 256) hist[i] = 0;
    __syncthreads();
#pragma unroll
    for (int e = 0; e < CH; e++) {
        unsigned k = keys[e * 256 + tid];
        if ((k >> 21) == b1) atomicAdd(&hist[(k >> 10) & 0x7FFu], 1);
    }
    __syncthreads();
    find_cross<2048>(hist, wsum, nd2, tid, lane, wid, &s_bin, &s_need);
    __syncthreads();
    unsigned pre21 = (b1 << 11) | (unsigned)s_bin;
    int nd3 = s_need;
    __syncthreads();

    for (int i = tid; i < 1024; i += 256) hist[i] = 0;
    __syncthreads();
#pragma unroll
    for (int e = 0; e < CH; e++) {
        unsigned k = keys[e * 256 + tid];
        if ((k >> 10) == pre21) atomicAdd(&hist[k & 0x3FFu], 1);
    }
    __syncthreads();
    find_cross<1024>(hist, wsum, nd3, tid, lane, wid, &s_bin, &s_need);
    __syncthreads();
    unsigned T = (pre21 << 10) | (unsigned)s_bin;
    int need_eq = s_need;
    __syncthreads();

    int cg = 0, ce = 0;
#pragma unroll
    for (int e = 0; e < CH; e++) {
        unsigned k = keys[e * 256 + tid];
        cg += (k > T);
        ce += (k == T);
    }
    {
        int v = (cg << 16) | ce;
#pragma unroll
        for (int d = 1; d < 32; d <<= 1) {
            int n = __shfl_up_sync(0xffffffffu, v, d);
            if (lane >= d) v += n;
        }
        if (lane == 31) wsum[wid] = v;
        __syncthreads();
        if (tid < 8) {
            int w = wsum[tid];
#pragma unroll
            for (int d = 1; d < 8; d <<= 1) {
                int n = __shfl_up_sync(0xffu, w, d);
                if (tid >= d) w += n;
            }
            wsum[tid] = w;
        }
        __syncthreads();
        int incl = v + (wid ? wsum[wid - 1] : 0);
        int total = wsum[7];
        int total_g = total >> 16;
        int pg = (incl >> 16) - cg;
        int pe = total_g + ((incl & 0xFFFF) - ce);
#pragma unroll
        for (int e = 0; e < CH; e++) {
            int gi = e * 256 + tid;
            unsigned k = keys[gi];
            if (k > T) {
                outv[pg] = key2f(k); outi[pg] = gi; pg++;
            } else if (k == T) {
                if (pe < total_g + need_eq) { outv[pe] = key2f(k); outi[pe] = gi; }
                pe++;
            }
        }
    }
    __syncthreads();
    if (tid < 32) {
        float s = outv[tid];
        for (int o = 16; o; o >>= 1) s += __shfl_xor_sync(0xffffffffu, s, o);
        if (tid == 0) s_invd = 1.f / fmaxf(s, 1e-5f);
    }
    __syncthreads();
    if (tid < TOPK) {
        g_tkw[row * TOPK + tid] = outv[tid] * s_invd;
        g_tki[row * TOPK + tid] = outi[tid];
    }
}

// ------------------- gemm v4: 2*HOUT threads, RPB=16, 4-buffer cp.async ring -------------------
template<int K, int HOUT>
__global__ void __launch_bounds__(2 * HOUT) gemm_t4(const float* __restrict__ A1,
                                                    const float* __restrict__ A2,
                                                    const float* __restrict__ W,
                                                    const float* __restrict__ bias, int act,
                                                    int accum,
                                                    float* __restrict__ C) {
    const int RPB = 16;
    const int BLK = 2 * HOUT;
    const int CHK = 2048 / HOUT;
    const int NCH = K / CHK;
    const int CBYTES = CHK * HOUT * 4;
    extern __shared__ float dyn[];
    float* wring = dyn;
    float* a_sh  = dyn + 4 * CHK * HOUT;
    uint32_t wsm = smem_u32(wring);

    int tid = threadIdx.x;
    int f  = tid & (HOUT - 1);
    int rh = tid / HOUT;
    int r0 = blockIdx.x * RPB;
    int rbase = rh * 8;

#pragma unroll
    for (int c = 0; c < 2; c++) {
        const float* gW = W + (size_t)c * CHK * HOUT;
        uint32_t dst = wsm + c * CBYTES;
        for (int i = tid; i < CHK * HOUT / 4; i += BLK)
            cp16(dst + (uint32_t)i * 16, gW + (size_t)i * 4);
        CP_COMMIT();
    }

    if (K == 256) {
        for (int idx = tid; idx < RPB * 128; idx += BLK) {
            int r = idx >> 7, k = idx & 127;
            a_sh[r * K + k]       = A1[(size_t)(r0 + r) * 128 + k];
            a_sh[r * K + 128 + k] = A2[(size_t)(r0 + r) * 128 + k];
        }
    } else {
        for (int idx = tid; idx < RPB * K; idx += BLK) {
            int r = idx / K, k = idx & (K - 1);
            a_sh[r * K + k] = A1[(size_t)(r0 + r) * K + k];
        }
    }

    float acc[8];
    if (accum) {
#pragma unroll
        for (int r = 0; r < 8; r++) acc[r] = C[(size_t)(r0 + rbase + r) * HOUT + f];
    } else {
        float b = bias ? bias[f] : 0.f;
#pragma unroll
        for (int r = 0; r < 8; r++) acc[r] = b;
    }

#pragma unroll
    for (int ch = 0; ch < NCH; ch++) {
        if (ch + 2 < NCH) {
            const float* gW = W + (size_t)(ch + 2) * CHK * HOUT;
            uint32_t dst = wsm + ((ch + 2) & 3) * CBYTES;
            for (int i = tid; i < CHK * HOUT / 4; i += BLK)
                cp16(dst + (uint32_t)i * 16, gW + (size_t)i * 4);
        }
        CP_COMMIT();
        CP_WAIT2();
        __syncthreads();

        const float* wp = wring + (ch & 3) * CHK * HOUT;
        int kc = ch * CHK;
#pragma unroll
        for (int kk = 0; kk < CHK; kk += 4) {
            float w0 = wp[kk * HOUT + f];
            float w1 = wp[(kk + 1) * HOUT + f];
            float w2 = wp[(kk + 2) * HOUT + f];
            float w3 = wp[(kk + 3) * HOUT + f];
#pragma unroll
            for (int r = 0; r < 8; r++) {
                float4 av = *(const float4*)&a_sh[(rbase + r) * K + kc + kk];
                acc[r] += av.x * w0 + av.y * w1 + av.z * w2 + av.w * w3;
            }
        }
    }

#pragma unroll
    for (int r = 0; r < 8; r++) {
        float v = acc[r];
        if (act) v = v > 0.f ? v : expm1f(v);
        C[(size_t)(r0 + rbase + r) * HOUT + f] = v;
    }
}

#define G4_128_128 ((4 * 16 * 128 + 16 * 128) * 4)
#define G4_128_256 ((4 * 8 * 256 + 16 * 128) * 4)

// ------------------- fused SAGE: 256 threads, RPB=16 -------------------
__global__ void __launch_bounds__(256) sage_fused(const float* __restrict__ z,
                                                  const float* __restrict__ h,
                                                  const float* __restrict__ W,
                                                  float* __restrict__ C) {
    const int RPB = 16, K = 256, HOUT = 128, BLK = 256;
    const int CHK = 16, NCH = 16;
    const int CBYTES = CHK * HOUT * 4;
    extern __shared__ float dyn[];
    float* wring = dyn;
    float* a_sh  = dyn + 4 * CHK * HOUT;
    float* twv   = a_sh + RPB * K;
    int*   twi   = (int*)(twv + RPB * TOPK);
    uint32_t wsm = smem_u32(wring);

    int tid = threadIdx.x;
    int f  = tid & 127;
    int rh = tid >> 7;
    int r0 = blockIdx.x * RPB;
    int rbase = rh * 8;

#pragma unroll
    for (int c = 0; c < 2; c++) {
        const float* gW = W + (size_t)c * CHK * HOUT;
        uint32_t dst = wsm + c * CBYTES;
        for (int i = tid; i < CHK * HOUT / 4; i += BLK)
            cp16(dst + (uint32_t)i * 16, gW + (size_t)i * 4);
        CP_COMMIT();
    }

    for (int i = tid; i < RPB * TOPK; i += BLK) {
        twv[i] = g_tkw[r0 * TOPK + i];
        twi[i] = g_tki[r0 * TOPK + i];
    }
#pragma unroll
    for (int r = 0; r < 8; r++)
        a_sh[(rbase + r) * K + f] = z[(size_t)(r0 + rbase + r) * 128 + f];
    __syncthreads();

#pragma unroll
    for (int r = 0; r < 8; r++) {
        int rr = rbase + r;
        float acc = 0.f;
#pragma unroll 8
        for (int q = 0; q < TOPK; q++)
            acc += twv[rr * TOPK + q] * h[(size_t)twi[rr * TOPK + q] * 128 + f];
        a_sh[rr * K + 128 + f] = acc;
    }

    float acc[8];
#pragma unroll
    for (int r = 0; r < 8; r++) acc[r] = 0.f;

#pragma unroll
    for (int ch = 0; ch < NCH; ch++) {
        if (ch + 2 < NCH) {
            const float* gW = W + (size_t)(ch + 2) * CHK * HOUT;
            uint32_t dst = wsm + ((ch + 2) & 3) * CBYTES;
            for (int i = tid; i < CHK * HOUT / 4; i += BLK)
                cp16(dst + (uint32_t)i * 16, gW + (size_t)i * 4);
        }
        CP_COMMIT();
        CP_WAIT2();
        __syncthreads();

        const float* wp = wring + (ch & 3) * CHK * HOUT;
        int kc = ch * CHK;
#pragma unroll
        for (int kk = 0; kk < CHK; kk += 4) {
            float w0 = wp[kk * HOUT + f];
            float w1 = wp[(kk + 1) * HOUT + f];
            float w2 = wp[(kk + 2) * HOUT + f];
            float w3 = wp[(kk + 3) * HOUT + f];
#pragma unroll
            for (int r = 0; r < 8; r++) {
                float4 av = *(const float4*)&a_sh[(rbase + r) * K + kc + kk];
                acc[r] += av.x * w0 + av.y * w1 + av.z * w2 + av.w * w3;
            }
        }
    }

#pragma unroll
    for (int r = 0; r < 8; r++) {
        float v = acc[r];
        v = v > 0.f ? v : expm1f(v);
        C[(size_t)(r0 + rbase + r) * HOUT + f] = v;
    }
}
#define SAGE_SMEM ((4 * 16 * 128 + 16 * 256 + 2 * 16 * 32) * 4)

// ------------------- GCN SpMM -------------------
__global__ void gcn_spmm(const float* __restrict__ zw, float* __restrict__ out) {
    int row = blockIdx.x, f = threadIdx.x;
    __shared__ float vv[MAXNNZ];
    __shared__ int   vi[MAXNNZ];
    int nnz = g_nnz[row];
    for (int i = f; i < nnz; i += H) {
        int j = g_nbr_idx[row * MAXNNZ + i];
        vi[i] = j;
        vv[i] = g_nbr_val[row * MAXNNZ + i] * g_isc[j];
    }
    __syncthreads();
    float acc = g_isc[row] * zw[(size_t)row * H + f];
    for (int i = 0; i < nnz; i++) acc += vv[i] * zw[(size_t)vi[i] * H + f];
    float v = acc * g_isr[row];
    out[(size_t)row * H + f] = v > 0.f ? v : expm1f(v);
}

// ------------------- edge logits -------------------
__global__ void edge_kernel(const int* __restrict__ src, const int* __restrict__ dst,
                            const float* __restrict__ g, const float* __restrict__ h1,
                            const float* __restrict__ h2, const float* __restrict__ predB,
                            float* __restrict__ logits) {
    int e = (blockIdx.x * blockDim.x + threadIdx.x) >> 5;
    int lane = threadIdx.x & 31;
    if (e >= E_EDGES) return;
    int s = src[e], d = dst[e];
    const float* gr = g + (size_t)s * (2 * H);
    float acc = 0.f;
#pragma unroll
    for (int u = 0; u < 8; u++) {
        int c = lane + 32 * u;
        float hv = (c < H) ? h1[(size_t)d * H + c] : h2[(size_t)d * H + (c - H)];
        acc += gr[c] * hv;
    }
    for (int o = 16; o; o >>= 1) acc += __shfl_xor_sync(0xffffffffu, acc, o);
    if (lane == 0) logits[e] = acc + predB[0];
}

// ------------------- BCE loss -------------------
__global__ void loss_kernel(const float* __restrict__ logits, const float* __restrict__ labels,
                            float* __restrict__ out) {
    __shared__ float sh[256];
    int tid = threadIdx.x;
    float s = 0.f;
    for (int e = tid; e < E_EDGES; e += 256) {
        float l = logits[e], y = labels[e];
        s += fmaxf(l, 0.f) - l * y + log1pf(expf(-fabsf(l)));
    }
    sh[tid] = s;
    __syncthreads();
    for (int st = 128; st >= 1; st >>= 1) {
        if (tid < st) sh[tid] += sh[tid + st];
        __syncthreads();
    }
    if (tid == 0) out[0] = sh[0] / (float)E_EDGES;
}

// ------------------- streams/events -------------------
struct StreamPack {
    cudaStream_t s2 = nullptr, s3 = nullptr;
    cudaEvent_t evRoot = nullptr, evGCN = nullptr, evP1 = nullptr;
    bool ok = false;
    StreamPack() {
        if (cudaStreamCreateWithFlags(&s2, cudaStreamNonBlocking) != cudaSuccess) return;
        if (cudaStreamCreateWithFlags(&s3, cudaStreamNonBlocking) != cudaSuccess) return;
        if (cudaEventCreateWithFlags(&evRoot, cudaEventDisableTiming) != cudaSuccess) return;
        if (cudaEventCreateWithFlags(&evGCN, cudaEventDisableTiming) != cudaSuccess) return;
        if (cudaEventCreateWithFlags(&evP1, cudaEventDisableTiming) != cudaSuccess) return;
        ok = true;
    }
};
static StreamPack g_sp;

// ------------------- launch -------------------
extern "C" void kernel_launch(void* const* d_in, const int* in_sizes, int n_in,
                              void* d_out, int out_size) {
    const int*   src    = (const int*)d_in[0];
    const int*   dst    = (const int*)d_in[1];
    const float* labels = (const float*)d_in[2];
    const float* adj    = (const float*)d_in[3];
    const float* x      = (const float*)d_in[4];
    const float* Wg1    = (const float*)d_in[5];
    const float* Wg2    = (const float*)d_in[6];
    const float* Wp1    = (const float*)d_in[7];
    const float* b1     = (const float*)d_in[8];
    const float* Ws1    = (const float*)d_in[9];
    const float* Wp2    = (const float*)d_in[10];
    const float* b2     = (const float*)d_in[11];
    const float* Ws2    = (const float*)d_in[12];
    const float* PredW  = (const float*)d_in[13];
    const float* PredB  = (const float*)d_in[14];
    float* out = (float*)d_out;

    float *bufA, *bufB, *bufD, *bufE, *bufF, *gg;
    cudaGetSymbolAddress((void**)&bufA, g_bufA);
    cudaGetSymbolAddress((void**)&bufB, g_bufB);
    cudaGetSymbolAddress((void**)&bufD, g_bufD);
    cudaGetSymbolAddress((void**)&bufE, g_bufE);
    cudaGetSymbolAddress((void**)&bufF, g_bufF);
    cudaGetSymbolAddress((void**)&gg,   g_g);

    cudaFuncSetAttribute(simgemm_mma, cudaFuncAttributeMaxDynamicSharedMemorySize, SIM_SMEM);
    cudaFuncSetAttribute(gemm_t4<128, 128>, cudaFuncAttributeMaxDynamicSharedMemorySize, G4_128_128);
    cudaFuncSetAttribute(gemm_t4<128, 256>, cudaFuncAttributeMaxDynamicSharedMemorySize, G4_128_256);
    cudaFuncSetAttribute(sage_fused, cudaFuncAttributeMaxDynamicSharedMemorySize, SAGE_SMEM);

    bool forked = g_sp.ok;
    cudaStream_t s2 = forked ? g_sp.s2 : (cudaStream_t)0;
    cudaStream_t s3 = forked ? g_sp.s3 : (cudaStream_t)0;

    if (forked) {
        cudaEventRecord(g_sp.evRoot, 0);
        cudaStreamWaitEvent(s2, g_sp.evRoot, 0);
        cudaStreamWaitEvent(s3, g_sp.evRoot, 0);
    }

    // --- side stream s2: adjacency + GCN branch -> bufB, then head half g = h1 @ PredW_top ---
    zero_colcnt<<<N / 256, 256, 0, s2>>>();
    build_csr<<<N / 8, 256, 0, s2>>>(adj);
    colcnt_to_isc<<<N / 256, 256, 0, s2>>>();
    gemm_t4<128, 128><<<N / 16, 256, G4_128_128, s2>>>(x,    nullptr, Wg1, nullptr, 0, 0, bufA);
    gcn_spmm<<<N, 128, 0, s2>>>(bufA, bufB);
    gemm_t4<128, 128><<<N / 16, 256, G4_128_128, s2>>>(bufB, nullptr, Wg2, nullptr, 0, 0, bufA);
    gcn_spmm<<<N, 128, 0, s2>>>(bufA, bufB);
    gemm_t4<128, 256><<<N / 16, 512, G4_128_256, s2>>>(bufB, nullptr, PredW, nullptr, 0, 0, gg);
    if (forked) cudaEventRecord(g_sp.evGCN, s2);

    // --- side stream s3: SAGE layer-1 projection -> bufE ---
    gemm_t4<128, 128><<<N / 16, 256, G4_128_128, s3>>>(x, nullptr, Wp1, b1, 1, 0, bufE);
    if (forked) cudaEventRecord(g_sp.evP1, s3);

    // --- main stream: sim graph ---
    norm_split<<<N / 8, 256>>>(x);
    simgemm_mma<<<2352, 256, SIM_SMEM>>>();
    topk_kernel<<<N, 256>>>();

    if (forked) cudaStreamWaitEvent(0, g_sp.evP1, 0);
    // --- SAGE branch (fused agg+gemm) -> bufF ---
    sage_fused<<<N / 16, 256, SAGE_SMEM>>>(x, bufE, Ws1, bufD);
    gemm_t4<128, 128><<<N / 16, 256, G4_128_128>>>(bufD, nullptr, Wp2, b2, 1, 0, bufE);
    sage_fused<<<N / 16, 256, SAGE_SMEM>>>(bufD, bufE, Ws2, bufF);

    if (forked) cudaStreamWaitEvent(0, g_sp.evGCN, 0);
    // --- head second half: g += h2 @ PredW_bottom ---
    gemm_t4<128, 256><<<N / 16, 512, G4_128_256>>>(bufF, nullptr, PredW + 128 * 256, nullptr, 0, 1, gg);
    edge_kernel<<<(E_EDGES * 32) / 256, 256>>>(src, dst, gg, bufB, bufF, PredB, out + 1);
    loss_kernel<<<1, 256>>>(out + 1, labels, out);
}